// round 13
// baseline (speedup 1.0000x reference)
#include <cuda_runtime.h>
#include <cstdint>

#define N_NODES 100000
#define N_EDGES 1600000
#define D 64
#define VEC_PER_ROW 16     // 64 floats = 16 float4
#define CAP 64             // per-node capacity; P(deg>=64)~1e-17 for Poisson(16)
#define PAD 68             // smem row stride (floats)

// ---------------------------------------------------------------------------
// Scratch (device globals; zero-initialized at module load, and the gather
// kernel re-zeroes g_cursor each call so every graph replay starts clean).
// ---------------------------------------------------------------------------
__device__ int g_cursor[N_NODES];          // doubles as degree count
__device__ int g_ssrc[N_NODES * CAP];      // 25.6 MB bucketed src ids

// ---------------------------------------------------------------------------
// 1) place: slot = atomicAdd(cursor[dst]); ssrc[dst*CAP + slot] = src
//    8 edges per thread so the ATOMGs (lat ~318) pipeline deeply.
// ---------------------------------------------------------------------------
__global__ void __launch_bounds__(256)
place_kernel(const int4* __restrict__ src4, const int4* __restrict__ dst4) {
    int i = blockIdx.x * blockDim.x + threadIdx.x;
    if (i >= N_EDGES / 8) return;
    int4 s0 = __ldg(&src4[i * 2 + 0]);
    int4 s1 = __ldg(&src4[i * 2 + 1]);
    int4 d0 = __ldg(&dst4[i * 2 + 0]);
    int4 d1 = __ldg(&dst4[i * 2 + 1]);
    int p0 = atomicAdd(&g_cursor[d0.x], 1);
    int p1 = atomicAdd(&g_cursor[d0.y], 1);
    int p2 = atomicAdd(&g_cursor[d0.z], 1);
    int p3 = atomicAdd(&g_cursor[d0.w], 1);
    int p4 = atomicAdd(&g_cursor[d1.x], 1);
    int p5 = atomicAdd(&g_cursor[d1.y], 1);
    int p6 = atomicAdd(&g_cursor[d1.z], 1);
    int p7 = atomicAdd(&g_cursor[d1.w], 1);
    if (p0 < CAP) g_ssrc[d0.x * CAP + p0] = s0.x;
    if (p1 < CAP) g_ssrc[d0.y * CAP + p1] = s0.y;
    if (p2 < CAP) g_ssrc[d0.z * CAP + p2] = s0.z;
    if (p3 < CAP) g_ssrc[d0.w * CAP + p3] = s0.w;
    if (p4 < CAP) g_ssrc[d1.x * CAP + p4] = s1.x;
    if (p5 < CAP) g_ssrc[d1.y * CAP + p5] = s1.y;
    if (p6 < CAP) g_ssrc[d1.z * CAP + p6] = s1.z;
    if (p7 < CAP) g_ssrc[d1.w * CAP + p7] = s1.w;
}

// ---------------------------------------------------------------------------
// 2) fused gather + transform (+ cursor reset for the next replay).
// Block = 256 threads = 16 groups of 16 lanes; group g owns one node.
// Gather: 8-edge unroll, index int4s software-pipelined one iteration ahead
// so the steady state always has 8 independent 256B feature loads in flight
// with no index->feature serial chain.
// ---------------------------------------------------------------------------
__global__ void __launch_bounds__(256)
gather_transform_kernel(const float4* __restrict__ feat4,
                        const float*  __restrict__ W,
                        const float4* __restrict__ b4,
                        float4*       __restrict__ out4) {
    __shared__ float Wt[D * PAD];        // Wt[k*PAD + j] = W[j*64 + k]
    __shared__ float rowsh[16 * PAD];    // one h row per group

    int tid = threadIdx.x;

    #pragma unroll 4
    for (int i = tid; i < D * D; i += 256) {
        int j = i >> 6;
        int k = i & 63;
        Wt[k * PAD + j] = W[i];
    }
    __syncthreads();

    int grp  = tid >> 4;
    int p    = tid & 15;
    int node = blockIdx.x * 16 + grp;    // grid sized exactly

    int deg = min(g_cursor[node], CAP);
    if (p == 0) g_cursor[node] = 0;      // reset for next graph replay
    const int4* sl4 = reinterpret_cast<const int4*>(g_ssrc + node * CAP);

    float4 a0 = make_float4(0.f, 0.f, 0.f, 0.f);
    float4 a1 = a0, a2 = a0, a3 = a0;

    int e = 0;
    int4 ua, ub;
    if (deg >= 8) {                      // prime the index pipeline
        ua = __ldg(&sl4[0]);
        ub = __ldg(&sl4[1]);
    }
    while (e + 8 <= deg) {
        int4 ca = ua, cb = ub;
        int en = e + 8;
        if (en + 8 <= deg) {             // prefetch next iteration's indices
            ua = __ldg(&sl4[(en >> 2) + 0]);
            ub = __ldg(&sl4[(en >> 2) + 1]);
        }
        float4 f0 = __ldg(&feat4[(size_t)ca.x * VEC_PER_ROW + p]);
        float4 f1 = __ldg(&feat4[(size_t)ca.y * VEC_PER_ROW + p]);
        float4 f2 = __ldg(&feat4[(size_t)ca.z * VEC_PER_ROW + p]);
        float4 f3 = __ldg(&feat4[(size_t)ca.w * VEC_PER_ROW + p]);
        float4 f4 = __ldg(&feat4[(size_t)cb.x * VEC_PER_ROW + p]);
        float4 f5 = __ldg(&feat4[(size_t)cb.y * VEC_PER_ROW + p]);
        float4 f6 = __ldg(&feat4[(size_t)cb.z * VEC_PER_ROW + p]);
        float4 f7 = __ldg(&feat4[(size_t)cb.w * VEC_PER_ROW + p]);
        a0.x += f0.x; a0.y += f0.y; a0.z += f0.z; a0.w += f0.w;
        a1.x += f1.x; a1.y += f1.y; a1.z += f1.z; a1.w += f1.w;
        a2.x += f2.x; a2.y += f2.y; a2.z += f2.z; a2.w += f2.w;
        a3.x += f3.x; a3.y += f3.y; a3.z += f3.z; a3.w += f3.w;
        a0.x += f4.x; a0.y += f4.y; a0.z += f4.z; a0.w += f4.w;
        a1.x += f5.x; a1.y += f5.y; a1.z += f5.z; a1.w += f5.w;
        a2.x += f6.x; a2.y += f6.y; a2.z += f6.z; a2.w += f6.w;
        a3.x += f7.x; a3.y += f7.y; a3.z += f7.z; a3.w += f7.w;
        e = en;
    }
    if (e + 4 <= deg) {
        int4 ca = __ldg(&sl4[e >> 2]);
        float4 f0 = __ldg(&feat4[(size_t)ca.x * VEC_PER_ROW + p]);
        float4 f1 = __ldg(&feat4[(size_t)ca.y * VEC_PER_ROW + p]);
        float4 f2 = __ldg(&feat4[(size_t)ca.z * VEC_PER_ROW + p]);
        float4 f3 = __ldg(&feat4[(size_t)ca.w * VEC_PER_ROW + p]);
        a0.x += f0.x; a0.y += f0.y; a0.z += f0.z; a0.w += f0.w;
        a1.x += f1.x; a1.y += f1.y; a1.z += f1.z; a1.w += f1.w;
        a2.x += f2.x; a2.y += f2.y; a2.z += f2.z; a2.w += f2.w;
        a3.x += f3.x; a3.y += f3.y; a3.z += f3.z; a3.w += f3.w;
        e += 4;
    }
    const int* sl = g_ssrc + node * CAP;
    for (; e < deg; e++) {
        int u = __ldg(&sl[e]);
        float4 f = __ldg(&feat4[(size_t)u * VEC_PER_ROW + p]);
        a0.x += f.x; a0.y += f.y; a0.z += f.z; a0.w += f.w;
    }

    float4 h;
    h.x = (a0.x + a1.x) + (a2.x + a3.x);
    h.y = (a0.y + a1.y) + (a2.y + a3.y);
    h.z = (a0.z + a1.z) + (a2.z + a3.z);
    h.w = (a0.w + a1.w) + (a2.w + a3.w);

    *reinterpret_cast<float4*>(&rowsh[grp * PAD + 4 * p]) = h;
    __syncwarp();

    float4 acc = __ldg(&b4[p]);
    const float* hr = &rowsh[grp * PAD];
    #pragma unroll 16
    for (int k = 0; k < D; k++) {
        float hk = hr[k];                                        // broadcast
        float4 w = *reinterpret_cast<const float4*>(&Wt[k * PAD + 4 * p]);
        acc.x = fmaf(hk, w.x, acc.x);
        acc.y = fmaf(hk, w.y, acc.y);
        acc.z = fmaf(hk, w.z, acc.z);
        acc.w = fmaf(hk, w.w, acc.w);
    }
    out4[(size_t)node * VEC_PER_ROW + p] = acc;
}

// ---------------------------------------------------------------------------
// Launch (2 kernels: cursors arrive zeroed — static init on first call,
// reset by gather_transform_kernel on every call thereafter)
// ---------------------------------------------------------------------------
extern "C" void kernel_launch(void* const* d_in, const int* in_sizes, int n_in,
                              void* d_out, int out_size) {
    const float* feature = (const float*)d_in[0];   // [100000, 64]
    const int*   src     = (const int*)  d_in[1];   // [1600000]
    const int*   dst     = (const int*)  d_in[2];   // [1600000]
    const float* W       = (const float*)d_in[3];   // [64, 64]
    const float* b       = (const float*)d_in[4];   // [64]
    float*       out     = (float*)d_out;           // [100000, 64]

    int othreads = N_EDGES / 8;                     // 200000
    place_kernel<<<(othreads + 255) / 256, 256>>>((const int4*)src,
                                                  (const int4*)dst);

    gather_transform_kernel<<<N_NODES / 16, 256>>>((const float4*)feature,
                                                   W, (const float4*)b,
                                                   (float4*)out);
}